// round 2
// baseline (speedup 1.0000x reference)
#include <cuda_runtime.h>
#include <cuda_bf16.h>
#include <math.h>

// ---------------- problem constants ----------------
#define Bc   2
#define Tc   1024
#define Ec   2048
#define Hc   16
#define Gc   4
#define HSc  128
#define Lc   4
#define Vc   32000
#define FFc  8192
#define QKVc ((Hc + 2*Gc) * HSc)   // 3072
#define NTc  (Bc * Tc)             // 2048 tokens
#define EPSc 1e-5f

// ---------------- scratch (static device globals; no allocs) ----------------
__device__ float g_x  [(size_t)NTc * Ec];     // residual stream
__device__ float g_xn [(size_t)NTc * Ec];     // normed activations
__device__ float g_qkv[(size_t)NTc * QKVc];   // fused qkv
__device__ float g_att[(size_t)NTc * Hc*HSc]; // attention output
__device__ float g_ffh[(size_t)NTc * FFc];    // mlp hidden

// ---------------- embed ----------------
__global__ void embed_kernel(const int* __restrict__ idx,
                             const float* __restrict__ wte,
                             float* __restrict__ x) {
    size_t i = (size_t)blockIdx.x * blockDim.x + threadIdx.x;
    if (i < (size_t)NTc * Ec) {
        int tok = (int)(i / Ec);
        int e   = (int)(i % Ec);
        x[i] = wte[(size_t)idx[tok] * Ec + e];
    }
}

// ---------------- rmsnorm (block per token) ----------------
__global__ void __launch_bounds__(256) rmsnorm_kernel(const float* __restrict__ x,
                                                      const float* __restrict__ w,
                                                      float* __restrict__ out) {
    int t = blockIdx.x;
    const float* xr = x + (size_t)t * Ec;
    float s = 0.f;
    for (int i = threadIdx.x; i < Ec; i += 256) { float v = xr[i]; s += v * v; }
    // block reduce
    __shared__ float sh[8];
    int lane = threadIdx.x & 31, warp = threadIdx.x >> 5;
    #pragma unroll
    for (int o = 16; o > 0; o >>= 1) s += __shfl_xor_sync(0xffffffffu, s, o);
    if (lane == 0) sh[warp] = s;
    __syncthreads();
    float tot = sh[0] + sh[1] + sh[2] + sh[3] + sh[4] + sh[5] + sh[6] + sh[7];
    float inv = rsqrtf(tot / (float)Ec + EPSc);
    float* orow = out + (size_t)t * Ec;
    for (int i = threadIdx.x; i < Ec; i += 256) orow[i] = xr[i] * inv * w[i];
}

// ---------------- rope (in-place on qkv; block per (token, head)) ----------------
__global__ void rope_kernel(float* __restrict__ qkv) {
    int token = blockIdx.x;          // 0..NT-1
    int hh    = blockIdx.y;          // 0..H+G-1 (q heads then k heads)
    int i     = threadIdx.x;         // 0..63 (pair index)
    int t     = token % Tc;          // sequence position
    size_t off = (size_t)token * QKVc + (hh < Hc ? hh * HSc : Hc * HSc + (hh - Hc) * HSc);
    float* base = qkv + off;
    float inv_freq = powf(10000.f, -(float)i / 64.f);
    float ang = (float)t * inv_freq;
    float sn, cs;
    sincosf(ang, &sn, &cs);
    float x1 = base[i], x2 = base[i + 64];
    base[i]      = x1 * cs - x2 * sn;
    base[i + 64] = x2 * cs + x1 * sn;
}

// ---------------- attention (block per (tq, h, b); 128 threads) ----------------
__global__ void __launch_bounds__(128) attn_kernel(const float* __restrict__ qkv,
                                                   float* __restrict__ y) {
    int tq = blockIdx.x, h = blockIdx.y, b = blockIdx.z;
    int g = h >> 2;  // H/G = 4
    int tid = threadIdx.x, lane = tid & 31, warp = tid >> 5;
    __shared__ float sq[HSc];
    __shared__ float sp[Tc];
    __shared__ float red[4];
    const float scale = 0.08838834764831845f;  // 1/sqrt(128)

    const float* qrow = qkv + ((size_t)(b * Tc + tq)) * QKVc + h * HSc;
    sq[tid] = qrow[tid];
    __syncthreads();

    int nk = tq + 1;
    float4 qv = ((const float4*)sq)[lane];

    // scores: one warp per key, lane covers 4 dims
    for (int s = warp; s < nk; s += 4) {
        const float* krow = qkv + ((size_t)(b * Tc + s)) * QKVc + Hc * HSc + g * HSc;
        float4 kv = ((const float4*)krow)[lane];
        float d = kv.x * qv.x + kv.y * qv.y + kv.z * qv.z + kv.w * qv.w;
        #pragma unroll
        for (int o = 16; o > 0; o >>= 1) d += __shfl_xor_sync(0xffffffffu, d, o);
        if (lane == 0) sp[s] = d * scale;
    }
    __syncthreads();

    // max
    float m = -1e30f;
    for (int s = tid; s < nk; s += 128) m = fmaxf(m, sp[s]);
    #pragma unroll
    for (int o = 16; o > 0; o >>= 1) m = fmaxf(m, __shfl_xor_sync(0xffffffffu, m, o));
    if (lane == 0) red[warp] = m;
    __syncthreads();
    m = fmaxf(fmaxf(red[0], red[1]), fmaxf(red[2], red[3]));
    __syncthreads();  // everyone done reading red before it is rewritten

    // exp + sum
    float lsum = 0.f;
    for (int s = tid; s < nk; s += 128) { float e = expf(sp[s] - m); sp[s] = e; lsum += e; }
    #pragma unroll
    for (int o = 16; o > 0; o >>= 1) lsum += __shfl_xor_sync(0xffffffffu, lsum, o);
    if (lane == 0) red[warp] = lsum;
    __syncthreads();
    float inv = 1.f / (red[0] + red[1] + red[2] + red[3]);

    // output: thread = head dim
    float acc = 0.f;
    const float* vbase = qkv + (size_t)(b * Tc) * QKVc + Hc * HSc + Gc * HSc + g * HSc + tid;
    int s = 0;
    for (; s + 4 <= nk; s += 4) {
        float p0 = sp[s], p1 = sp[s+1], p2 = sp[s+2], p3 = sp[s+3];
        acc += p0 * vbase[(size_t)(s    ) * QKVc];
        acc += p1 * vbase[(size_t)(s + 1) * QKVc];
        acc += p2 * vbase[(size_t)(s + 2) * QKVc];
        acc += p3 * vbase[(size_t)(s + 3) * QKVc];
    }
    for (; s < nk; s++) acc += sp[s] * vbase[(size_t)s * QKVc];

    y[((size_t)(b * Tc + tq)) * (Hc * HSc) + h * HSc + tid] = acc * inv;
}

// ---------------- gelu (tanh approx, matches jax.nn.gelu default) ----------------
__device__ __forceinline__ float gelu_tanh(float x) {
    const float k0 = 0.7978845608028654f;  // sqrt(2/pi)
    float x3 = x * x * x;
    return 0.5f * x * (1.f + tanhf(k0 * (x + 0.044715f * x3)));
}

// ---------------- SGEMM: C[M,N] = A[M,K] @ W[N,K]^T  (EPI: 0=store 1=C+=  2=gelu) ----
// BM=BN=128, BK=16, 256 threads, 8x8 per thread. All dims multiples of 128/16.
template <int EPI>
__global__ void __launch_bounds__(256) sgemm_kernel(const float* __restrict__ A,
                                                    const float* __restrict__ W,
                                                    float* __restrict__ C,
                                                    int M, int N, int K) {
    __shared__ float As[16][128];
    __shared__ float Bs[16][128];
    int tid = threadIdx.x;
    int tx = tid & 15, ty = tid >> 4;
    int m0 = blockIdx.y * 128, n0 = blockIdx.x * 128;

    float acc[8][8];
    #pragma unroll
    for (int i = 0; i < 8; i++)
        #pragma unroll
        for (int j = 0; j < 8; j++) acc[i][j] = 0.f;

    const float* Ap = A + (size_t)m0 * K;
    const float* Wp = W + (size_t)n0 * K;

    for (int k0 = 0; k0 < K; k0 += 16) {
        #pragma unroll
        for (int it = 0; it < 2; it++) {
            int e = tid + it * 256;
            int row = e >> 2;   // 0..127
            int c4  = e & 3;    // 0..3
            float4 a = *(const float4*)(Ap + (size_t)row * K + k0 + c4 * 4);
            As[c4*4 + 0][row] = a.x; As[c4*4 + 1][row] = a.y;
            As[c4*4 + 2][row] = a.z; As[c4*4 + 3][row] = a.w;
            float4 b = *(const float4*)(Wp + (size_t)row * K + k0 + c4 * 4);
            Bs[c4*4 + 0][row] = b.x; Bs[c4*4 + 1][row] = b.y;
            Bs[c4*4 + 2][row] = b.z; Bs[c4*4 + 3][row] = b.w;
        }
        __syncthreads();
        #pragma unroll
        for (int kk = 0; kk < 16; kk++) {
            float af[8], bf[8];
            float4 a0 = *(const float4*)&As[kk][ty * 8];
            float4 a1 = *(const float4*)&As[kk][ty * 8 + 4];
            float4 b0 = *(const float4*)&Bs[kk][tx * 8];
            float4 b1 = *(const float4*)&Bs[kk][tx * 8 + 4];
            af[0]=a0.x; af[1]=a0.y; af[2]=a0.z; af[3]=a0.w;
            af[4]=a1.x; af[5]=a1.y; af[6]=a1.z; af[7]=a1.w;
            bf[0]=b0.x; bf[1]=b0.y; bf[2]=b0.z; bf[3]=b0.w;
            bf[4]=b1.x; bf[5]=b1.y; bf[6]=b1.z; bf[7]=b1.w;
            #pragma unroll
            for (int i = 0; i < 8; i++)
                #pragma unroll
                for (int j = 0; j < 8; j++)
                    acc[i][j] += af[i] * bf[j];
        }
        __syncthreads();
    }

    #pragma unroll
    for (int i = 0; i < 8; i++) {
        int m = m0 + ty * 8 + i;
        float* crow = C + (size_t)m * N + n0 + tx * 8;
        #pragma unroll
        for (int j = 0; j < 8; j++) {
            float v = acc[i][j];
            if (EPI == 1) v += crow[j];
            if (EPI == 2) v = gelu_tanh(v);
            crow[j] = v;
        }
    }
}

// ---------------- launcher ----------------
extern "C" void kernel_launch(void* const* d_in, const int* in_sizes, int n_in,
                              void* d_out, int out_size) {
    const int*   idx  = (const int*)  d_in[0];
    const float* wte  = (const float*)d_in[1];
    const float* qkvw = (const float*)d_in[2];
    const float* apw  = (const float*)d_in[3];
    const float* fcw  = (const float*)d_in[4];
    const float* mpw  = (const float*)d_in[5];
    const float* n1w  = (const float*)d_in[6];
    const float* n2w  = (const float*)d_in[7];
    const float* lnfw = (const float*)d_in[8];
    const float* lmw  = (const float*)d_in[9];
    float* out = (float*)d_out;
    (void)in_sizes; (void)n_in; (void)out_size;

    float *x, *xn, *qkv, *att, *ffh;
    cudaGetSymbolAddress((void**)&x,   g_x);
    cudaGetSymbolAddress((void**)&xn,  g_xn);
    cudaGetSymbolAddress((void**)&qkv, g_qkv);
    cudaGetSymbolAddress((void**)&att, g_att);
    cudaGetSymbolAddress((void**)&ffh, g_ffh);

    embed_kernel<<<((size_t)NTc * Ec + 255) / 256, 256>>>(idx, wte, x);

    for (int l = 0; l < Lc; l++) {
        // attn
        rmsnorm_kernel<<<NTc, 256>>>(x, n1w + (size_t)l * Ec, xn);
        sgemm_kernel<0><<<dim3(QKVc / 128, NTc / 128), 256>>>(
            xn, qkvw + (size_t)l * QKVc * Ec, qkv, NTc, QKVc, Ec);
        rope_kernel<<<dim3(NTc, Hc + Gc), 64>>>(qkv);
        attn_kernel<<<dim3(Tc, Hc, Bc), 128>>>(qkv, att);
        sgemm_kernel<1><<<dim3(Ec / 128, NTc / 128), 256>>>(
            att, apw + (size_t)l * Ec * (Hc * HSc), x, NTc, Ec, Hc * HSc);
        // mlp
        rmsnorm_kernel<<<NTc, 256>>>(x, n2w + (size_t)l * Ec, xn);
        sgemm_kernel<2><<<dim3(FFc / 128, NTc / 128), 256>>>(
            xn, fcw + (size_t)l * FFc * Ec, ffh, NTc, FFc, Ec);
        sgemm_kernel<1><<<dim3(Ec / 128, NTc / 128), 256>>>(
            ffh, mpw + (size_t)l * Ec * FFc, x, NTc, Ec, FFc);
    }

    rmsnorm_kernel<<<NTc, 256>>>(x, lnfw, xn);
    sgemm_kernel<0><<<dim3(Vc / 128, NTc / 128), 256>>>(xn, lmw, out, NTc, Vc, Ec);
}

// round 4
// speedup vs baseline: 2.9409x; 2.9409x over previous
#include <cuda_runtime.h>
#include <cuda_bf16.h>
#include <math.h>
#include <stdint.h>

// ---------------- problem constants ----------------
#define Bc   2
#define Tc   1024
#define Ec   2048
#define Hc   16
#define Gc   4
#define HSc  128
#define Lc   4
#define Vc   32000
#define FFc  8192
#define QKVc ((Hc + 2*Gc) * HSc)   // 3072
#define NTc  (Bc * Tc)             // 2048 tokens
#define EPSc 1e-5f

// ---------------- scratch (static device globals; no allocs) ----------------
__device__ float g_x  [(size_t)NTc * Ec];
__device__ float g_xn [(size_t)NTc * Ec];
__device__ float g_qkv[(size_t)NTc * QKVc];
__device__ float g_att[(size_t)NTc * Hc*HSc];
__device__ float g_ffh[(size_t)NTc * FFc];
// rounded-to-tf32 weight copies
__device__ float g_wqkv[(size_t)Lc * QKVc * Ec];
__device__ float g_wap [(size_t)Lc * Ec * Hc * HSc];
__device__ float g_wfc [(size_t)Lc * FFc * Ec];
__device__ float g_wmp [(size_t)Lc * Ec * FFc];
__device__ float g_wlm [(size_t)Vc * Ec];

// ---------------- tf32 round-to-nearest ----------------
__device__ __forceinline__ float to_tf32(float x) {
    uint32_t u;
    asm("cvt.rna.tf32.f32 %0, %1;" : "=r"(u) : "f"(x));
    return __uint_as_float(u);
}

__device__ __forceinline__ uint32_t smem_u32(const void* p) {
    uint32_t a;
    asm("{ .reg .u64 t; cvta.to.shared.u64 t, %1; cvt.u32.u64 %0, t; }" : "=r"(a) : "l"(p));
    return a;
}
__device__ __forceinline__ void cp16(uint32_t dst, const void* src) {
    asm volatile("cp.async.cg.shared.global [%0], [%1], 16;" :: "r"(dst), "l"(src));
}
__device__ __forceinline__ void ldsm4(uint32_t& r0, uint32_t& r1, uint32_t& r2, uint32_t& r3,
                                      uint32_t addr) {
    asm volatile("ldmatrix.sync.aligned.m8n8.x4.shared.b16 {%0,%1,%2,%3}, [%4];"
                 : "=r"(r0), "=r"(r1), "=r"(r2), "=r"(r3) : "r"(addr));
}
__device__ __forceinline__ void mma_tf32(float* d, uint32_t a0, uint32_t a1, uint32_t a2,
                                         uint32_t a3, uint32_t b0, uint32_t b1) {
    asm volatile(
        "mma.sync.aligned.m16n8k8.row.col.f32.tf32.tf32.f32 "
        "{%0,%1,%2,%3}, {%4,%5,%6,%7}, {%8,%9}, {%0,%1,%2,%3};"
        : "+f"(d[0]), "+f"(d[1]), "+f"(d[2]), "+f"(d[3])
        : "r"(a0), "r"(a1), "r"(a2), "r"(a3), "r"(b0), "r"(b1));
}
// 16B-granular XOR swizzle within a [rows][32 floats] tile (128B rows)
__device__ __forceinline__ uint32_t swz(uint32_t off) {
    return off ^ (((off >> 7) & 7) << 4);
}

// ---------------- gelu (tanh approx) ----------------
__device__ __forceinline__ float gelu_tanh(float x) {
    const float k0 = 0.7978845608028654f;
    float x3 = x * x * x;
    return 0.5f * x * (1.f + tanhf(k0 * (x + 0.044715f * x3)));
}

// =====================================================================
// tf32 mma.sync GEMM: C[M,N] = A[M,K] @ W[N,K]^T
// BM=BN=128, BK=32, 3-stage cp.async, 256 threads, warp grid 2x4,
// warp tile 64x32 (4 m16-tiles x 4 n8-tiles), m16n8k8.tf32 MMAs.
// EPI: 0 = store, 1 = C += (residual), 2 = gelu (+tf32 round)
// =====================================================================
#define GNS 3
#define GBM 128
#define GBN 128
#define GBK 32
#define STAGE_BYTES 32768           // 16KB A + 16KB B
#define GEMM_SMEM (GNS * STAGE_BYTES)   // 98304

template <int EPI>
__global__ void __launch_bounds__(256) tc_gemm(const float* __restrict__ A,
                                               const float* __restrict__ W,
                                               float* __restrict__ C,
                                               int M, int N, int K) {
    extern __shared__ char smem[];
    uint32_t sb = smem_u32(smem);
    int tid = threadIdx.x;
    int lane = tid & 31, wid = tid >> 5;
    int wm = wid & 1, wn = wid >> 1;            // 2x4 warp grid
    int m0 = blockIdx.y * GBM, n0 = blockIdx.x * GBN;
    int NC = K / GBK;

    const float* Ab = A + (size_t)m0 * K;
    const float* Wb = W + (size_t)n0 * K;

    float acc[4][4][4];
    #pragma unroll
    for (int i = 0; i < 4; i++)
        #pragma unroll
        for (int j = 0; j < 4; j++)
            #pragma unroll
            for (int r = 0; r < 4; r++) acc[i][j][r] = 0.f;

    // ldsm address components (within-tile)
    int rowA = wm * 64 + (lane & 15);
    int khA  = lane >> 4;                        // 0/1 -> k-half
    int rowB = wn * 32 + ((lane & 16) >> 1) + (lane & 7);
    int khB  = (lane >> 3) & 1;

    auto load_chunk = [&](int c) {
        int s = c % GNS;
        uint32_t as = sb + s * STAGE_BYTES;
        uint32_t bs = as + 16384;
        const float* Ac = Ab + c * GBK;
        const float* Wc = Wb + c * GBK;
        #pragma unroll
        for (int i = 0; i < 4; i++) {
            int t = tid + i * 256;
            int r = t >> 3, ch = t & 7;
            uint32_t off = (uint32_t)(r * 128) + (uint32_t)((ch ^ (r & 7)) * 16);
            cp16(as + off, Ac + (size_t)r * K + ch * 4);
            cp16(bs + off, Wc + (size_t)r * K + ch * 4);
        }
    };

    for (int c = 0; c < GNS - 1; c++) {
        load_chunk(c);
        asm volatile("cp.async.commit_group;" ::: "memory");
    }

    for (int c = 0; c < NC; c++) {
        asm volatile("cp.async.wait_group %0;" :: "n"(GNS - 2) : "memory");
        __syncthreads();

        // prefetch next stage
        if (c + GNS - 1 < NC) load_chunk(c + GNS - 1);
        asm volatile("cp.async.commit_group;" ::: "memory");

        uint32_t aBase = sb + (c % GNS) * STAGE_BYTES;
        uint32_t bBase = aBase + 16384;

        #pragma unroll
        for (int ks = 0; ks < 4; ks++) {
            uint32_t bf0[4], bf1[4];
            {
                uint32_t r0, r1, r2, r3;
                ldsm4(r0, r1, r2, r3,
                      bBase + swz((uint32_t)(rowB * 128 + ks * 32 + khB * 16)));
                bf0[0] = r0; bf1[0] = r1; bf0[1] = r2; bf1[1] = r3;
                ldsm4(r0, r1, r2, r3,
                      bBase + swz((uint32_t)((rowB + 16) * 128 + ks * 32 + khB * 16)));
                bf0[2] = r0; bf1[2] = r1; bf0[3] = r2; bf1[3] = r3;
            }
            #pragma unroll
            for (int mt = 0; mt < 4; mt++) {
                uint32_t a0, a1, a2, a3;
                ldsm4(a0, a1, a2, a3,
                      aBase + swz((uint32_t)((rowA + mt * 16) * 128 + ks * 32 + khA * 16)));
                #pragma unroll
                for (int nt = 0; nt < 4; nt++)
                    mma_tf32(acc[mt][nt], a0, a1, a2, a3, bf0[nt], bf1[nt]);
            }
        }
        __syncthreads();
    }

    // ---- epilogue ----
    int gr = lane >> 2, gc2 = (lane & 3) * 2;
    #pragma unroll
    for (int mt = 0; mt < 4; mt++) {
        int r0 = m0 + wm * 64 + mt * 16 + gr;
        #pragma unroll
        for (int nt = 0; nt < 4; nt++) {
            int cc = n0 + wn * 32 + nt * 8 + gc2;
            float* p0 = C + (size_t)r0 * N + cc;
            float* p1 = p0 + (size_t)8 * N;
            float v0 = acc[mt][nt][0], v1 = acc[mt][nt][1];
            float v2 = acc[mt][nt][2], v3 = acc[mt][nt][3];
            if (EPI == 1) {
                float2 o0 = *(float2*)p0, o1 = *(float2*)p1;
                v0 += o0.x; v1 += o0.y; v2 += o1.x; v3 += o1.y;
            }
            if (EPI == 2) {
                v0 = to_tf32(gelu_tanh(v0)); v1 = to_tf32(gelu_tanh(v1));
                v2 = to_tf32(gelu_tanh(v2)); v3 = to_tf32(gelu_tanh(v3));
            }
            *(float2*)p0 = make_float2(v0, v1);
            *(float2*)p1 = make_float2(v2, v3);
        }
    }
}

// ---------------- weight round-to-tf32 ----------------
__global__ void round_w_kernel(const float* __restrict__ in, float* __restrict__ out, size_t n4) {
    size_t i = (size_t)blockIdx.x * blockDim.x + threadIdx.x;
    if (i < n4) {
        float4 v = ((const float4*)in)[i];
        v.x = to_tf32(v.x); v.y = to_tf32(v.y); v.z = to_tf32(v.z); v.w = to_tf32(v.w);
        ((float4*)out)[i] = v;
    }
}

// ---------------- embed ----------------
__global__ void embed_kernel(const int* __restrict__ idx,
                             const float* __restrict__ wte,
                             float* __restrict__ x) {
    size_t i = (size_t)blockIdx.x * blockDim.x + threadIdx.x;
    if (i < (size_t)NTc * Ec) {
        int tok = (int)(i / Ec);
        int e   = (int)(i % Ec);
        x[i] = wte[(size_t)idx[tok] * Ec + e];
    }
}

// ---------------- rmsnorm (block per token), output rounded to tf32 ----------------
__global__ void __launch_bounds__(256) rmsnorm_kernel(const float* __restrict__ x,
                                                      const float* __restrict__ w,
                                                      float* __restrict__ out) {
    int t = blockIdx.x;
    const float* xr = x + (size_t)t * Ec;
    float s = 0.f;
    for (int i = threadIdx.x; i < Ec; i += 256) { float v = xr[i]; s += v * v; }
    __shared__ float sh[8];
    int lane = threadIdx.x & 31, warp = threadIdx.x >> 5;
    #pragma unroll
    for (int o = 16; o > 0; o >>= 1) s += __shfl_xor_sync(0xffffffffu, s, o);
    if (lane == 0) sh[warp] = s;
    __syncthreads();
    float tot = sh[0] + sh[1] + sh[2] + sh[3] + sh[4] + sh[5] + sh[6] + sh[7];
    float inv = rsqrtf(tot / (float)Ec + EPSc);
    float* orow = out + (size_t)t * Ec;
    for (int i = threadIdx.x; i < Ec; i += 256) orow[i] = to_tf32(xr[i] * inv * w[i]);
}

// ---------------- rope (in-place on qkv) ----------------
__global__ void rope_kernel(float* __restrict__ qkv) {
    int token = blockIdx.x;
    int hh    = blockIdx.y;
    int i     = threadIdx.x;
    int t     = token % Tc;
    size_t off = (size_t)token * QKVc + (hh < Hc ? hh * HSc : Hc * HSc + (hh - Hc) * HSc);
    float* base = qkv + off;
    float inv_freq = powf(10000.f, -(float)i / 64.f);
    float ang = (float)t * inv_freq;
    float sn, cs;
    sincosf(ang, &sn, &cs);
    float x1 = base[i], x2 = base[i + 64];
    base[i]      = x1 * cs - x2 * sn;
    base[i + 64] = x2 * cs + x1 * sn;
}

// ---------------- attention (block per (tq, h, b)), output rounded to tf32 --------
__global__ void __launch_bounds__(128) attn_kernel(const float* __restrict__ qkv,
                                                   float* __restrict__ y) {
    int tq = blockIdx.x, h = blockIdx.y, b = blockIdx.z;
    int g = h >> 2;
    int tid = threadIdx.x, lane = tid & 31, warp = tid >> 5;
    __shared__ float sq[HSc];
    __shared__ float sp[Tc];
    __shared__ float red[4];
    const float scale = 0.08838834764831845f;

    const float* qrow = qkv + ((size_t)(b * Tc + tq)) * QKVc + h * HSc;
    sq[tid] = qrow[tid];
    __syncthreads();

    int nk = tq + 1;
    float4 qv = ((const float4*)sq)[lane];

    for (int s = warp; s < nk; s += 4) {
        const float* krow = qkv + ((size_t)(b * Tc + s)) * QKVc + Hc * HSc + g * HSc;
        float4 kv = ((const float4*)krow)[lane];
        float d = kv.x * qv.x + kv.y * qv.y + kv.z * qv.z + kv.w * qv.w;
        #pragma unroll
        for (int o = 16; o > 0; o >>= 1) d += __shfl_xor_sync(0xffffffffu, d, o);
        if (lane == 0) sp[s] = d * scale;
    }
    __syncthreads();

    float m = -1e30f;
    for (int s = tid; s < nk; s += 128) m = fmaxf(m, sp[s]);
    #pragma unroll
    for (int o = 16; o > 0; o >>= 1) m = fmaxf(m, __shfl_xor_sync(0xffffffffu, m, o));
    if (lane == 0) red[warp] = m;
    __syncthreads();
    m = fmaxf(fmaxf(red[0], red[1]), fmaxf(red[2], red[3]));
    __syncthreads();

    float lsum = 0.f;
    for (int s = tid; s < nk; s += 128) { float e = expf(sp[s] - m); sp[s] = e; lsum += e; }
    #pragma unroll
    for (int o = 16; o > 0; o >>= 1) lsum += __shfl_xor_sync(0xffffffffu, lsum, o);
    if (lane == 0) red[warp] = lsum;
    __syncthreads();
    float inv = 1.f / (red[0] + red[1] + red[2] + red[3]);

    float acc = 0.f;
    const float* vbase = qkv + (size_t)(b * Tc) * QKVc + Hc * HSc + Gc * HSc + g * HSc + tid;
    int s = 0;
    for (; s + 4 <= nk; s += 4) {
        acc += sp[s]   * vbase[(size_t)(s    ) * QKVc];
        acc += sp[s+1] * vbase[(size_t)(s + 1) * QKVc];
        acc += sp[s+2] * vbase[(size_t)(s + 2) * QKVc];
        acc += sp[s+3] * vbase[(size_t)(s + 3) * QKVc];
    }
    for (; s < nk; s++) acc += sp[s] * vbase[(size_t)s * QKVc];

    y[((size_t)(b * Tc + tq)) * (Hc * HSc) + h * HSc + tid] = to_tf32(acc * inv);
}

// ---------------- launcher ----------------
static void launch_gemm(int epi, const float* A, const float* W, float* C,
                        int M, int N, int K) {
    dim3 grid(N / GBN, M / GBM);
    if (epi == 0) tc_gemm<0><<<grid, 256, GEMM_SMEM>>>(A, W, C, M, N, K);
    else if (epi == 1) tc_gemm<1><<<grid, 256, GEMM_SMEM>>>(A, W, C, M, N, K);
    else tc_gemm<2><<<grid, 256, GEMM_SMEM>>>(A, W, C, M, N, K);
}

extern "C" void kernel_launch(void* const* d_in, const int* in_sizes, int n_in,
                              void* d_out, int out_size) {
    const int*   idx  = (const int*)  d_in[0];
    const float* wte  = (const float*)d_in[1];
    const float* qkvw = (const float*)d_in[2];
    const float* apw  = (const float*)d_in[3];
    const float* fcw  = (const float*)d_in[4];
    const float* mpw  = (const float*)d_in[5];
    const float* n1w  = (const float*)d_in[6];
    const float* n2w  = (const float*)d_in[7];
    const float* lnfw = (const float*)d_in[8];
    const float* lmw  = (const float*)d_in[9];
    float* out = (float*)d_out;
    (void)in_sizes; (void)n_in; (void)out_size;

    float *x, *xn, *qkv, *att, *ffh;
    float *wq, *wa, *wf, *wm, *wl;
    cudaGetSymbolAddress((void**)&x,   g_x);
    cudaGetSymbolAddress((void**)&xn,  g_xn);
    cudaGetSymbolAddress((void**)&qkv, g_qkv);
    cudaGetSymbolAddress((void**)&att, g_att);
    cudaGetSymbolAddress((void**)&ffh, g_ffh);
    cudaGetSymbolAddress((void**)&wq,  g_wqkv);
    cudaGetSymbolAddress((void**)&wa,  g_wap);
    cudaGetSymbolAddress((void**)&wf,  g_wfc);
    cudaGetSymbolAddress((void**)&wm,  g_wmp);
    cudaGetSymbolAddress((void**)&wl,  g_wlm);

    cudaFuncSetAttribute(tc_gemm<0>, cudaFuncAttributeMaxDynamicSharedMemorySize, GEMM_SMEM);
    cudaFuncSetAttribute(tc_gemm<1>, cudaFuncAttributeMaxDynamicSharedMemorySize, GEMM_SMEM);
    cudaFuncSetAttribute(tc_gemm<2>, cudaFuncAttributeMaxDynamicSharedMemorySize, GEMM_SMEM);

    // round all weights to nearest-tf32 (removes HW-truncation bias)
    {
        size_t n;
        n = (size_t)Lc * QKVc * Ec / 4;
        round_w_kernel<<<(unsigned)((n + 255) / 256), 256>>>(qkvw, wq, n);
        n = (size_t)Lc * Ec * Hc * HSc / 4;
        round_w_kernel<<<(unsigned)((n + 255) / 256), 256>>>(apw, wa, n);
        n = (size_t)Lc * FFc * Ec / 4;
        round_w_kernel<<<(unsigned)((n + 255) / 256), 256>>>(fcw, wf, n);
        n = (size_t)Lc * Ec * FFc / 4;
        round_w_kernel<<<(unsigned)((n + 255) / 256), 256>>>(mpw, wm, n);
        n = (size_t)Vc * Ec / 4;
        round_w_kernel<<<(unsigned)((n + 255) / 256), 256>>>(lmw, wl, n);
    }

    embed_kernel<<<((size_t)NTc * Ec + 255) / 256, 256>>>(idx, wte, x);

    for (int l = 0; l < Lc; l++) {
        rmsnorm_kernel<<<NTc, 256>>>(x, n1w + (size_t)l * Ec, xn);
        launch_gemm(0, xn, wq + (size_t)l * QKVc * Ec, qkv, NTc, QKVc, Ec);
        rope_kernel<<<dim3(NTc, Hc + Gc), 64>>>(qkv);
        attn_kernel<<<dim3(Tc, Hc, Bc), 128>>>(qkv, att);
        launch_gemm(1, att, wa + (size_t)l * Ec * (Hc * HSc), x, NTc, Ec, Hc * HSc);
        rmsnorm_kernel<<<NTc, 256>>>(x, n2w + (size_t)l * Ec, xn);
        launch_gemm(2, xn, wf + (size_t)l * FFc * Ec, ffh, NTc, FFc, Ec);
        launch_gemm(1, ffh, wm + (size_t)l * Ec * FFc, x, NTc, Ec, FFc);
    }

    rmsnorm_kernel<<<NTc, 256>>>(x, lnfw, xn);
    launch_gemm(0, xn, wl, out, NTc, Vc, Ec);
}